// round 2
// baseline (speedup 1.0000x reference)
#include <cuda_runtime.h>

#define NB 8
#define NT 2048
#define NC 1024
#define NH 64

typedef unsigned long long u64;

__device__ __forceinline__ u64 pack2(float lo, float hi) {
    u64 r; asm("mov.b64 %0, {%1,%2};" : "=l"(r) : "f"(lo), "f"(hi)); return r;
}
__device__ __forceinline__ u64 bcast2(float v) { return pack2(v, v); }
__device__ __forceinline__ void ffma2(u64& d, u64 a, u64 b) {
    asm("fma.rn.f32x2 %0, %1, %2, %3;" : "=l"(d) : "l"(a), "l"(b), "l"(d));
}
__device__ __forceinline__ u64 mul2(u64 a, u64 b) {
    u64 d; asm("mul.rn.f32x2 %0, %1, %2;" : "=l"(d) : "l"(a), "l"(b)); return d;
}
__device__ __forceinline__ float2 unpk(u64 v) {
    float2 f; asm("mov.b64 {%0,%1}, %2;" : "=f"(f.x), "=f"(f.y) : "l"(v)); return f;
}

// scratch (allocation-free rule: __device__ globals)
__device__ float g_q[NB * NT * NH];
__device__ float g_k[NB * NT * NH];
__device__ float g_v[NB * NT * NH];

// ---------------------------------------------------------------------------
// Projection with FFMA2: out[t][h] = sum_c x[t][c] * W[h][c]
// grid (128, 3), block 256 (16x16). Each thread: 8 tokens x 4 outs (2 pairs).
// x is stored into smem as DUPLICATED f32x2 pairs so the hot loop needs no
// packing movs: per kk = 8 LDS.64 (broadcast) + 1 LDS.128 + 16 FFMA2.
// ---------------------------------------------------------------------------
__global__ __launch_bounds__(256) void proj_kernel(
    const float* __restrict__ x, const float* __restrict__ Wk,
    const float* __restrict__ Wq, const float* __restrict__ Wv)
{
    __shared__ u64   xs2[128 * 33];   // xs2[token][c] = (x,x) duplicated
    __shared__ float wsT[32 * 68];    // wsT[c][o] transposed W chunk

    const float* __restrict__ W;
    float* out;
    if (blockIdx.y == 0)      { W = Wk; out = g_k; }
    else if (blockIdx.y == 1) { W = Wq; out = g_q; }
    else                      { W = Wv; out = g_v; }

    const int tid = threadIdx.x;
    const int tx = tid & 15, ty = tid >> 4;
    const int t0 = ty * 8;
    const int o0 = tx * 4;
    const long tile = (long)blockIdx.x * 128;

    u64 acc[8][2];
#pragma unroll
    for (int i = 0; i < 8; i++) { acc[i][0] = 0ull; acc[i][1] = 0ull; }

    for (int cc = 0; cc < NC; cc += 32) {
        // x tile -> duplicated pairs
#pragma unroll
        for (int k = 0; k < 4; k++) {
            int f4 = tid + 256 * k;
            int token = f4 >> 3, c4 = f4 & 7;
            float4 v = *(const float4*)(x + (tile + token) * NC + cc + c4 * 4);
            xs2[token * 33 + c4 * 4 + 0] = bcast2(v.x);
            xs2[token * 33 + c4 * 4 + 1] = bcast2(v.y);
            xs2[token * 33 + c4 * 4 + 2] = bcast2(v.z);
            xs2[token * 33 + c4 * 4 + 3] = bcast2(v.w);
        }
        // W chunk transposed
#pragma unroll
        for (int k = 0; k < 2; k++) {
            int f4 = tid + 256 * k;
            int o = f4 >> 3, k4 = f4 & 7;
            float4 v = *(const float4*)(W + (long)o * NC + cc + k4 * 4);
            wsT[(k4 * 4 + 0) * 68 + o] = v.x;
            wsT[(k4 * 4 + 1) * 68 + o] = v.y;
            wsT[(k4 * 4 + 2) * 68 + o] = v.z;
            wsT[(k4 * 4 + 3) * 68 + o] = v.w;
        }
        __syncthreads();

#pragma unroll 8
        for (int kk = 0; kk < 32; kk++) {
            const u64* wp = (const u64*)(wsT + kk * 68 + o0);
            u64 w01 = wp[0], w23 = wp[1];
#pragma unroll
            for (int i = 0; i < 8; i++) {
                u64 xb = xs2[(t0 + i) * 33 + kk];
                ffma2(acc[i][0], xb, w01);
                ffma2(acc[i][1], xb, w23);
            }
        }
        __syncthreads();
    }

#pragma unroll
    for (int i = 0; i < 8; i++) {
        float2 a = unpk(acc[i][0]);
        float2 c = unpk(acc[i][1]);
        *(float4*)(out + (tile + t0 + i) * NH + o0) = make_float4(a.x, a.y, c.x, c.y);
    }
}

// ---------------------------------------------------------------------------
// Flash attention, causal. Tq=64, Tk=128 per step. 512 threads (16 warps).
// QK layout: warp = rows r0..r0+3, lanes = col groups (c0=tx*4).
//   Register softmax: row max/sum via full-warp shfl_xor; m,l in registers.
// PV layout: rpv = tid>>3 (one row), o0=(tid&7)*8 (8 output cols as 4 pairs).
// Q/K stored transposed with XOR swizzle (^((h&7)<<2)) -> conflict-free LDS.
// Grid (16, 8): block handles q-tile pair (i, 31-i) => balanced 33 tiles.
// ---------------------------------------------------------------------------
__global__ __launch_bounds__(512, 1) void attn_kernel(float* __restrict__ out)
{
    extern __shared__ float sm[];
    float* Qt   = sm;           // 64h x 64r (swizzled r)      : 4096
    float* Kt   = sm + 4096;    // 64h x 128c (swizzled c)     : 8192
    float* Vs   = sm + 12288;   // 128s x 64o natural          : 8192
    float* P    = sm + 20480;   // 64r x 132                   : 8448
    float* frow = sm + 28928;   // 64
    float* lrow = sm + 28992;   // 64

    const int tid = threadIdx.x;
    const int b = blockIdx.y;
    // QK layout
    const int tx = tid & 31;
    const int r0 = (tid >> 5) * 4;
    const int c0 = tx * 4;
    // PV layout
    const int rpv = tid >> 3;
    const int o0 = (tid & 7) * 8;

#pragma unroll 1
    for (int pass = 0; pass < 2; pass++) {
        const int qt = pass ? (31 - (int)blockIdx.x) : (int)blockIdx.x;
        const int qbase = qt * 64;
        const float* qg = g_q + ((long)b * NT + qbase) * NH;

        // load Q (pre-scaled by HS^-0.5), transposed + swizzled
#pragma unroll
        for (int k = 0; k < 2; k++) {
            int f4 = tid + 512 * k;
            int r = f4 >> 4, h4 = f4 & 15;
            float4 v = *(const float4*)(qg + r * 64 + h4 * 4);
            float vv[4] = {v.x * 0.125f, v.y * 0.125f, v.z * 0.125f, v.w * 0.125f};
#pragma unroll
            for (int e = 0; e < 4; e++) {
                int h = h4 * 4 + e;
                Qt[h * 64 + (r ^ ((h & 7) << 2))] = vv[e];
            }
        }

        float mr[4], lr[4];
#pragma unroll
        for (int i = 0; i < 4; i++) { mr[i] = -1e30f; lr[i] = 0.f; }
        u64 O[4];
#pragma unroll
        for (int j = 0; j < 4; j++) O[j] = 0ull;

        const int nsteps = qt / 2 + 1;
        for (int k2 = 0; k2 < nsteps; k2++) {
            const int s0g = k2 * 128;
            // --- load K transposed+swizzled (u64 pair stores) ---
            const float* kg = g_k + ((long)b * NT + s0g) * NH;
#pragma unroll
            for (int k = 0; k < 2; k++) {
                int f = tid + 512 * k;
                int cp = f >> 4, h4 = f & 15;
                int c = cp * 2;
                float4 a0 = *(const float4*)(kg + c * 64 + h4 * 4);
                float4 a1 = *(const float4*)(kg + (c + 1) * 64 + h4 * 4);
                float av0[4] = {a0.x, a0.y, a0.z, a0.w};
                float av1[4] = {a1.x, a1.y, a1.z, a1.w};
#pragma unroll
                for (int e = 0; e < 4; e++) {
                    int h = h4 * 4 + e;
                    *(u64*)(Kt + h * 128 + (c ^ ((h & 7) << 2))) =
                        pack2(av0[e], av1[e]);
                }
            }
            // --- load V natural ---
            const float4* vg = (const float4*)(g_v + ((long)b * NT + s0g) * NH);
#pragma unroll
            for (int k = 0; k < 4; k++)
                ((float4*)Vs)[tid + 512 * k] = vg[tid + 512 * k];
            __syncthreads();

            // --- S = Q K^T (row pairs packed) ---
            u64 s0[4], s1[4];
#pragma unroll
            for (int j = 0; j < 4; j++) { s0[j] = 0ull; s1[j] = 0ull; }
#pragma unroll 4
            for (int h = 0; h < 64; h++) {
                int sw = (h & 7) << 2;
                const u64* qp = (const u64*)(Qt + h * 64 + (r0 ^ sw));
                float4 kf = *(const float4*)(Kt + h * 128 + (c0 ^ sw));
                u64 q01 = qp[0], q23 = qp[1];
                u64 kb;
                kb = bcast2(kf.x); ffma2(s0[0], q01, kb); ffma2(s1[0], q23, kb);
                kb = bcast2(kf.y); ffma2(s0[1], q01, kb); ffma2(s1[1], q23, kb);
                kb = bcast2(kf.z); ffma2(s0[2], q01, kb); ffma2(s1[2], q23, kb);
                kb = bcast2(kf.w); ffma2(s0[3], q01, kb); ffma2(s1[3], q23, kb);
            }

            // --- registerized online softmax (warp owns 4 rows) ---
            float vr[4][4];
#pragma unroll
            for (int j = 0; j < 4; j++) {
                float2 a = unpk(s0[j]);
                float2 c = unpk(s1[j]);
                vr[0][j] = a.x; vr[1][j] = a.y; vr[2][j] = c.x; vr[3][j] = c.y;
            }
            float fi4[4];
#pragma unroll
            for (int i = 0; i < 4; i++) {
                int rg = qbase + r0 + i;
#pragma unroll
                for (int j = 0; j < 4; j++)
                    if (s0g + c0 + j > rg) vr[i][j] = -1e30f;
                float m4 = fmaxf(fmaxf(vr[i][0], vr[i][1]),
                                 fmaxf(vr[i][2], vr[i][3]));
#pragma unroll
                for (int off = 16; off > 0; off >>= 1)
                    m4 = fmaxf(m4, __shfl_xor_sync(0xffffffffu, m4, off));
                float mnew = fmaxf(mr[i], m4);
                float fi = __expf(mr[i] - mnew);
                mr[i] = mnew;
                float p0 = __expf(vr[i][0] - mnew);
                float p1 = __expf(vr[i][1] - mnew);
                float p2 = __expf(vr[i][2] - mnew);
                float p3 = __expf(vr[i][3] - mnew);
                float rs = (p0 + p1) + (p2 + p3);
#pragma unroll
                for (int off = 16; off > 0; off >>= 1)
                    rs += __shfl_xor_sync(0xffffffffu, rs, off);
                lr[i] = lr[i] * fi + rs;
                fi4[i] = fi;
                *(float4*)(P + (r0 + i) * 132 + c0) = make_float4(p0, p1, p2, p3);
            }
            if (tx == 0) {
                frow[r0 + 0] = fi4[0]; frow[r0 + 1] = fi4[1];
                frow[r0 + 2] = fi4[2]; frow[r0 + 3] = fi4[3];
            }
            __syncthreads();

            // --- O = O*f + P V ---
            {
                u64 fb = bcast2(frow[rpv]);
#pragma unroll
                for (int j = 0; j < 4; j++) O[j] = mul2(O[j], fb);
                const float* Pr = P + rpv * 132;
#pragma unroll 4
                for (int s = 0; s < 128; s++) {
                    u64 pb = bcast2(Pr[s]);
                    const u64* vp = (const u64*)(Vs + s * 64 + o0);
                    ffma2(O[0], pb, vp[0]);
                    ffma2(O[1], pb, vp[1]);
                    ffma2(O[2], pb, vp[2]);
                    ffma2(O[3], pb, vp[3]);
                }
            }
            __syncthreads();
        }

        // --- epilogue: normalize + store ---
        if (tx == 0) {
            lrow[r0 + 0] = lr[0]; lrow[r0 + 1] = lr[1];
            lrow[r0 + 2] = lr[2]; lrow[r0 + 3] = lr[3];
        }
        __syncthreads();
        {
            float inv = 1.0f / lrow[rpv];
            float2 f0 = unpk(O[0]);
            float2 f1 = unpk(O[1]);
            float2 f2 = unpk(O[2]);
            float2 f3 = unpk(O[3]);
            float* og = out + ((long)b * NT + qbase + rpv) * NH + o0;
            *(float4*)og       = make_float4(f0.x * inv, f0.y * inv,
                                             f1.x * inv, f1.y * inv);
            *(float4*)(og + 4) = make_float4(f2.x * inv, f2.y * inv,
                                             f3.x * inv, f3.y * inv);
        }
        __syncthreads();   // protect smem before second pass reuses it
    }
}

extern "C" void kernel_launch(void* const* d_in, const int* in_sizes, int n_in,
                              void* d_out, int out_size)
{
    const float* x  = (const float*)d_in[0];
    const float* Wk = (const float*)d_in[1];
    const float* Wq = (const float*)d_in[2];
    const float* Wv = (const float*)d_in[3];
    float* out = (float*)d_out;

    proj_kernel<<<dim3(128, 3), 256>>>(x, Wk, Wq, Wv);

    const int smem_bytes = 29056 * 4;  // 116224
    cudaFuncSetAttribute(attn_kernel,
                         cudaFuncAttributeMaxDynamicSharedMemorySize, smem_bytes);
    attn_kernel<<<dim3(16, 8), 512, smem_bytes>>>(out);
}

// round 4
// speedup vs baseline: 3.2187x; 3.2187x over previous
#include <cuda_runtime.h>
#include <cuda_bf16.h>
#include <cstdint>

#define NB 8
#define NT 2048
#define NC 1024
#define NH 64
#define PSTR 36   // u64 row stride for all pair-tiles (32 k-pairs + 4 pad)

typedef unsigned long long u64;

// scratch (allocation-free rule: __device__ globals)
__device__ float g_q[NB * NT * NH];
__device__ float g_k[NB * NT * NH];
__device__ float g_v[NB * NT * NH];

// ---- bf16 hi/lo split helpers -------------------------------------------
// u64 layout: low 32 bits = (bf16 hi of k0 | hi of k1 << 16), high 32 = lo pair.
__device__ __forceinline__ u64 bsplit2(float a, float b) {
    __nv_bfloat162 h = __floats2bfloat162_rn(a, b);
    float2 hf = __bfloat1622float2(h);
    __nv_bfloat162 l = __floats2bfloat162_rn(a - hf.x, b - hf.y);
    uint32_t hu = *reinterpret_cast<uint32_t*>(&h);
    uint32_t lu = *reinterpret_cast<uint32_t*>(&l);
    u64 r;
    asm("mov.b64 %0, {%1,%2};" : "=l"(r) : "r"(hu), "r"(lu));
    return r;
}
__device__ __forceinline__ void up2(u64 v, uint32_t& h, uint32_t& l) {
    asm("mov.b64 {%0,%1}, %2;" : "=r"(h), "=r"(l) : "l"(v));
}
__device__ __forceinline__ void mma4(float* c, const uint32_t* a, const uint32_t* b) {
    asm volatile(
        "mma.sync.aligned.m16n8k16.row.col.f32.bf16.bf16.f32 "
        "{%0,%1,%2,%3}, {%4,%5,%6,%7}, {%8,%9}, {%0,%1,%2,%3};"
        : "+f"(c[0]), "+f"(c[1]), "+f"(c[2]), "+f"(c[3])
        : "r"(a[0]), "r"(a[1]), "r"(a[2]), "r"(a[3]), "r"(b[0]), "r"(b[1]));
}

// ---------------------------------------------------------------------------
// Projection: out[t][h] = sum_c x[t][c] * W[h][c], via bf16x2 split mma.sync.
// grid (128, 3): 128 M-tiles of 128 rows; y selects (Wk,Wq,Wv) -> (g_k,g_q,g_v).
// block 256 = 8 warps: warp_m = wid&3 (32 rows), warp_n = wid>>2 (32 cols).
// K chunks of 64, double-buffered smem, global loads staged through registers.
// ---------------------------------------------------------------------------
__global__ __launch_bounds__(256, 1) void proj_kernel(
    const float* __restrict__ x, const float* __restrict__ Wk,
    const float* __restrict__ Wq, const float* __restrict__ Wv)
{
    extern __shared__ u64 smp[];
    u64* Abuf = smp;                    // [2][128][PSTR]
    u64* Bbuf = smp + 2 * 128 * PSTR;   // [2][64][PSTR]

    const float* __restrict__ W;
    float* out;
    if (blockIdx.y == 0)      { W = Wk; out = g_k; }
    else if (blockIdx.y == 1) { W = Wq; out = g_q; }
    else                      { W = Wv; out = g_v; }

    const int tid = threadIdx.x;
    const int lane = tid & 31, wid = tid >> 5;
    const int g = lane >> 2, t = lane & 3;
    const int wm = wid & 3, wn = wid >> 2;
    const long tile = (long)blockIdx.x * 128;

    float acc[2][4][4];
#pragma unroll
    for (int i = 0; i < 2; i++)
#pragma unroll
        for (int j = 0; j < 4; j++)
#pragma unroll
            for (int e = 0; e < 4; e++) acc[i][j][e] = 0.f;

    float4 ra[8], rb[4];
    auto ldg_chunk = [&](int c) {
        const int k0 = c * 64;
#pragma unroll
        for (int it = 0; it < 8; it++) {
            int idx = tid + 256 * it;
            int r = idx >> 4, c4 = idx & 15;
            ra[it] = *(const float4*)(x + (tile + r) * NC + k0 + c4 * 4);
        }
#pragma unroll
        for (int it = 0; it < 4; it++) {
            int idx = tid + 256 * it;
            int r = idx >> 4, c4 = idx & 15;
            rb[it] = *(const float4*)(W + (long)r * NC + k0 + c4 * 4);
        }
    };
    auto sts_chunk = [&](int buf) {
        u64* Ab = Abuf + buf * 128 * PSTR;
        u64* Bb = Bbuf + buf * 64 * PSTR;
#pragma unroll
        for (int it = 0; it < 8; it++) {
            int idx = tid + 256 * it;
            int r = idx >> 4, c4 = idx & 15;
            ulonglong2 st;
            st.x = bsplit2(ra[it].x, ra[it].y);
            st.y = bsplit2(ra[it].z, ra[it].w);
            *reinterpret_cast<ulonglong2*>(&Ab[r * PSTR + 2 * c4]) = st;
        }
#pragma unroll
        for (int it = 0; it < 4; it++) {
            int idx = tid + 256 * it;
            int r = idx >> 4, c4 = idx & 15;
            ulonglong2 st;
            st.x = bsplit2(rb[it].x, rb[it].y);
            st.y = bsplit2(rb[it].z, rb[it].w);
            *reinterpret_cast<ulonglong2*>(&Bb[r * PSTR + 2 * c4]) = st;
        }
    };

    ldg_chunk(0);
    sts_chunk(0);
    __syncthreads();

    for (int c = 0; c < 16; c++) {
        if (c + 1 < 16) ldg_chunk(c + 1);

        const u64* Ab = Abuf + (c & 1) * 128 * PSTR;
        const u64* Bb = Bbuf + (c & 1) * 64 * PSTR;
#pragma unroll
        for (int ks = 0; ks < 4; ks++) {
            uint32_t ah[2][4], al[2][4];
#pragma unroll
            for (int i = 0; i < 2; i++) {
                int row = wm * 32 + i * 16 + g;
                up2(Ab[row * PSTR + 8 * ks + t],           ah[i][0], al[i][0]);
                up2(Ab[(row + 8) * PSTR + 8 * ks + t],     ah[i][1], al[i][1]);
                up2(Ab[row * PSTR + 8 * ks + t + 4],       ah[i][2], al[i][2]);
                up2(Ab[(row + 8) * PSTR + 8 * ks + t + 4], ah[i][3], al[i][3]);
            }
#pragma unroll
            for (int j = 0; j < 4; j++) {
                int n = wn * 32 + j * 8 + g;
                uint32_t bh[2], bl[2];
                up2(Bb[n * PSTR + 8 * ks + t],     bh[0], bl[0]);
                up2(Bb[n * PSTR + 8 * ks + t + 4], bh[1], bl[1]);
#pragma unroll
                for (int i = 0; i < 2; i++) {
                    mma4(acc[i][j], ah[i], bh);
                    mma4(acc[i][j], ah[i], bl);
                    mma4(acc[i][j], al[i], bh);
                }
            }
        }
        if (c + 1 < 16) sts_chunk((c + 1) & 1);
        __syncthreads();
    }

    // epilogue
#pragma unroll
    for (int i = 0; i < 2; i++)
#pragma unroll
        for (int j = 0; j < 4; j++) {
            long row = tile + wm * 32 + i * 16 + g;
            int col = wn * 32 + j * 8 + 2 * t;
            *(float2*)(out + row * NH + col) =
                make_float2(acc[i][j][0], acc[i][j][1]);
            *(float2*)(out + (row + 8) * NH + col) =
                make_float2(acc[i][j][2], acc[i][j][3]);
        }
}

// ---------------------------------------------------------------------------
// Flash attention (causal) with bf16x2 split mma.sync for QK^T and PV.
// Tq = Tk = 64. block 256 = 8 warps: warp_m = wid&3 (16 rows), warp_n = wid>>2
// (32 cols). Online softmax fully registerized (shfl over 4-lane groups +
// one smem exchange across the 2 warp_n halves). P stored to smem as hi/lo
// pairs directly from the mma accumulator layout.
// grid (16, 8): block handles q-tile pair (i, 31-i) -> balanced 33 steps.
// ---------------------------------------------------------------------------
__global__ __launch_bounds__(256, 1) void attn_kernel(float* __restrict__ out)
{
    extern __shared__ u64 sma[];
    u64* Qs = sma;                  // [64][PSTR]
    u64* Ks = Qs + 64 * PSTR;
    u64* Vt = Ks + 64 * PSTR;       // V^T: [o][s-pair]
    u64* Ps = Vt + 64 * PSTR;
    float* pmax = (float*)(Ps + 64 * PSTR);  // [64][2]
    float* psum = pmax + 128;                // [64][2]

    const int tid = threadIdx.x;
    const int lane = tid & 31, wid = tid >> 5;
    const int g = lane >> 2, t = lane & 3;
    const int wm = wid & 3, wn = wid >> 2;
    const int b = blockIdx.y;
    const int row0 = wm * 16 + g;        // within-tile rows owned by this thread
    const int row1 = row0 + 8;

#pragma unroll 1
    for (int pass = 0; pass < 2; pass++) {
        const int qt = pass ? (31 - (int)blockIdx.x) : (int)blockIdx.x;
        const int qbase = qt * 64;

        // ---- load Q (pre-scaled), split to bf16 pairs ----
        const float* qg = g_q + ((long)b * NT + qbase) * NH;
#pragma unroll
        for (int it = 0; it < 4; it++) {
            int idx = tid + 256 * it;
            int r = idx >> 4, c4 = idx & 15;
            float4 v = *(const float4*)(qg + r * 64 + c4 * 4);
            ulonglong2 st;
            st.x = bsplit2(v.x * 0.125f, v.y * 0.125f);
            st.y = bsplit2(v.z * 0.125f, v.w * 0.125f);
            *reinterpret_cast<ulonglong2*>(&Qs[r * PSTR + 2 * c4]) = st;
        }

        float mr0 = -1e30f, mr1 = -1e30f, lr0 = 0.f, lr1 = 0.f;
        float O[4][4];
#pragma unroll
        for (int j = 0; j < 4; j++)
#pragma unroll
            for (int e = 0; e < 4; e++) O[j][e] = 0.f;
        __syncthreads();

        for (int kt = 0; kt <= qt; kt++) {
            // ---- convert K tile ----
            const float* kg = g_k + ((long)b * NT + kt * 64) * NH;
#pragma unroll
            for (int it = 0; it < 4; it++) {
                int idx = tid + 256 * it;
                int r = idx >> 4, c4 = idx & 15;
                float4 v = *(const float4*)(kg + r * 64 + c4 * 4);
                ulonglong2 st;
                st.x = bsplit2(v.x, v.y);
                st.y = bsplit2(v.z, v.w);
                *reinterpret_cast<ulonglong2*>(&Ks[r * PSTR + 2 * c4]) = st;
            }
            // ---- convert V tile into V^T [o][s-pair] ----
            const float* vg = g_v + ((long)b * NT + kt * 64) * NH;
#pragma unroll
            for (int it = 0; it < 8; it++) {
                int idx2 = wid + 8 * it;             // 0..63
                int o = (idx2 & 7) * 8 + g;
                int sp = (idx2 >> 3) * 4 + t;
                float f0 = vg[(2 * sp) * 64 + o];
                float f1 = vg[(2 * sp + 1) * 64 + o];
                Vt[o * PSTR + sp] = bsplit2(f0, f1);
            }
            __syncthreads();

            // ---- S = Q K^T ----
            float s[4][4];
#pragma unroll
            for (int j = 0; j < 4; j++)
#pragma unroll
                for (int e = 0; e < 4; e++) s[j][e] = 0.f;
#pragma unroll
            for (int ks = 0; ks < 4; ks++) {
                uint32_t ah[4], al[4];
                up2(Qs[row0 * PSTR + 8 * ks + t],     ah[0], al[0]);
                up2(Qs[row1 * PSTR + 8 * ks + t],     ah[1], al[1]);
                up2(Qs[row0 * PSTR + 8 * ks + t + 4], ah[2], al[2]);
                up2(Qs[row1 * PSTR + 8 * ks + t + 4], ah[3], al[3]);
#pragma unroll
                for (int j = 0; j < 4; j++) {
                    int n = wn * 32 + j * 8 + g;
                    uint32_t bh[2], bl[2];
                    up2(Ks[n * PSTR + 8 * ks + t],     bh[0], bl[0]);
                    up2(Ks[n * PSTR + 8 * ks + t + 4], bh[1], bl[1]);
                    mma4(s[j], ah, bh);
                    mma4(s[j], ah, bl);
                    mma4(s[j], al, bh);
                }
            }

            // ---- causal mask on the diagonal tile ----
            if (kt == qt) {
#pragma unroll
                for (int j = 0; j < 4; j++) {
                    int col = wn * 32 + j * 8 + 2 * t;
                    if (col > row0)     s[j][0] = -1e30f;
                    if (col + 1 > row0) s[j][1] = -1e30f;
                    if (col > row1)     s[j][2] = -1e30f;
                    if (col + 1 > row1) s[j][3] = -1e30f;
                }
            }

            // ---- online softmax ----
            float mx0 = -1e30f, mx1 = -1e30f;
#pragma unroll
            for (int j = 0; j < 4; j++) {
                mx0 = fmaxf(mx0, fmaxf(s[j][0], s[j][1]));
                mx1 = fmaxf(mx1, fmaxf(s[j][2], s[j][3]));
            }
            mx0 = fmaxf(mx0, __shfl_xor_sync(0xffffffffu, mx0, 1));
            mx0 = fmaxf(mx0, __shfl_xor_sync(0xffffffffu, mx0, 2));
            mx1 = fmaxf(mx1, __shfl_xor_sync(0xffffffffu, mx1, 1));
            mx1 = fmaxf(mx1, __shfl_xor_sync(0xffffffffu, mx1, 2));
            if (t == 0) {
                pmax[row0 * 2 + wn] = mx0;
                pmax[row1 * 2 + wn] = mx1;
            }
            __syncthreads();
            float M0 = fmaxf(pmax[row0 * 2], pmax[row0 * 2 + 1]);
            float M1 = fmaxf(pmax[row1 * 2], pmax[row1 * 2 + 1]);
            float mn0 = fmaxf(mr0, M0), mn1 = fmaxf(mr1, M1);
            float f0 = __expf(mr0 - mn0), f1 = __expf(mr1 - mn1);
            mr0 = mn0; mr1 = mn1;

            float sum0 = 0.f, sum1 = 0.f;
#pragma unroll
            for (int j = 0; j < 4; j++) {
                float p0 = __expf(s[j][0] - mn0);
                float p1 = __expf(s[j][1] - mn0);
                float p2 = __expf(s[j][2] - mn1);
                float p3 = __expf(s[j][3] - mn1);
                sum0 += p0 + p1;
                sum1 += p2 + p3;
                int sp = wn * 16 + j * 4 + t;
                Ps[row0 * PSTR + sp] = bsplit2(p0, p1);
                Ps[row1 * PSTR + sp] = bsplit2(p2, p3);
                O[j][0] *= f0; O[j][1] *= f0;
                O[j][2] *= f1; O[j][3] *= f1;
            }
            sum0 += __shfl_xor_sync(0xffffffffu, sum0, 1);
            sum0 += __shfl_xor_sync(0xffffffffu, sum0, 2);
            sum1 += __shfl_xor_sync(0xffffffffu, sum1, 1);
            sum1 += __shfl_xor_sync(0xffffffffu, sum1, 2);
            lr0 = lr0 * f0 + sum0;
            lr1 = lr1 * f1 + sum1;
            __syncthreads();   // P visible to all warps

            // ---- O += P V ----
#pragma unroll
            for (int ks = 0; ks < 4; ks++) {
                uint32_t ah[4], al[4];
                up2(Ps[row0 * PSTR + 8 * ks + t],     ah[0], al[0]);
                up2(Ps[row1 * PSTR + 8 * ks + t],     ah[1], al[1]);
                up2(Ps[row0 * PSTR + 8 * ks + t + 4], ah[2], al[2]);
                up2(Ps[row1 * PSTR + 8 * ks + t + 4], ah[3], al[3]);
#pragma unroll
                for (int j = 0; j < 4; j++) {
                    int n = wn * 32 + j * 8 + g;
                    uint32_t bh[2], bl[2];
                    up2(Vt[n * PSTR + 8 * ks + t],     bh[0], bl[0]);
                    up2(Vt[n * PSTR + 8 * ks + t + 4], bh[1], bl[1]);
                    mma4(O[j], ah, bh);
                    mma4(O[j], ah, bl);
                    mma4(O[j], al, bh);
                }
            }
            __syncthreads();   // done reading K/V/P before next tile overwrites
        }

        // ---- epilogue ----
        if (t == 0) {
            psum[row0 * 2 + wn] = lr0;
            psum[row1 * 2 + wn] = lr1;
        }
        __syncthreads();
        float inv0 = 1.0f / (psum[row0 * 2] + psum[row0 * 2 + 1]);
        float inv1 = 1.0f / (psum[row1 * 2] + psum[row1 * 2 + 1]);
#pragma unroll
        for (int j = 0; j < 4; j++) {
            int col = wn * 32 + j * 8 + 2 * t;
            *(float2*)(out + ((long)b * NT + qbase + row0) * NH + col) =
                make_float2(O[j][0] * inv0, O[j][1] * inv0);
            *(float2*)(out + ((long)b * NT + qbase + row1) * NH + col) =
                make_float2(O[j][2] * inv1, O[j][3] * inv1);
        }
        __syncthreads();
    }
}

extern "C" void kernel_launch(void* const* d_in, const int* in_sizes, int n_in,
                              void* d_out, int out_size)
{
    const float* x  = (const float*)d_in[0];
    const float* Wk = (const float*)d_in[1];
    const float* Wq = (const float*)d_in[2];
    const float* Wv = (const float*)d_in[3];
    float* out = (float*)d_out;

    const int proj_smem = (2 * 128 * PSTR + 2 * 64 * PSTR) * 8;   // 110592
    cudaFuncSetAttribute(proj_kernel,
                         cudaFuncAttributeMaxDynamicSharedMemorySize, proj_smem);
    proj_kernel<<<dim3(128, 3), 256, proj_smem>>>(x, Wk, Wq, Wv);

    const int attn_smem = 4 * 64 * PSTR * 8 + 256 * 4;            // 74752
    cudaFuncSetAttribute(attn_kernel,
                         cudaFuncAttributeMaxDynamicSharedMemorySize, attn_smem);
    attn_kernel<<<dim3(16, 8), 256, attn_smem>>>(out);
}